// round 13
// baseline (speedup 1.0000x reference)
#include <cuda_runtime.h>
#include <cuda_fp16.h>
#include <cstdint>
#include <math.h>

#define BB_   32
#define DIM_  256
#define HEADS_ 8
#define KD_   16
#define DV_   64
#define NHKD_ 128
#define DH_   512
#define QKVO_ 768
#define WW_   28
#define NN_   784
#define EPSBN 1e-5f
#define SCALE_ 0.25f
#define LOG2E_ 1.4426950408889634f

// ---------------- scratch (fp16 intermediates) ----------------
__device__ __half g_qkv[(size_t)BB_ * QKVO_ * NN_ + 64];
__device__ __half g_qdw[(size_t)BB_ * NHKD_ * NN_ + 64];
__device__ __half g_att[(size_t)BB_ * DH_ * NN_ + 64];
__device__ __half g_x16[(size_t)BB_ * DIM_ * NN_ + 64];
__device__ __half g_wqkv[QKVO_ * DIM_];
__device__ __half g_wproj[DIM_ * DH_];

// ---------------- helpers ----------------
__device__ __forceinline__ float ex2f(float x) {
    float y; asm("ex2.approx.ftz.f32 %0, %1;" : "=f"(y) : "f"(x)); return y;
}
__device__ __forceinline__ unsigned fh2(float lo, float hi) {
    __half2 h = __floats2half2_rn(lo, hi);
    return *reinterpret_cast<unsigned*>(&h);
}
__device__ __forceinline__ unsigned h2u(__half2 h) {
    return *reinterpret_cast<unsigned*>(&h);
}
__device__ __forceinline__ void mma16(float4& c, const uint4& a, unsigned b0, unsigned b1) {
    asm volatile(
        "mma.sync.aligned.m16n8k16.row.col.f32.f16.f16.f32 "
        "{%0,%1,%2,%3},{%4,%5,%6,%7},{%8,%9},{%0,%1,%2,%3};"
        : "+f"(c.x), "+f"(c.y), "+f"(c.z), "+f"(c.w)
        : "r"(a.x), "r"(a.y), "r"(a.z), "r"(a.w), "r"(b0), "r"(b1));
}
__device__ __forceinline__ void ldmx2t(unsigned& r0, unsigned& r1, uint32_t addr) {
    asm volatile(
        "ldmatrix.sync.aligned.m8n8.x2.trans.shared.b16 {%0,%1}, [%2];"
        : "=r"(r0), "=r"(r1) : "r"(addr));
}
__device__ __forceinline__ void ldmx2(unsigned& r0, unsigned& r1, uint32_t addr) {
    asm volatile(
        "ldmatrix.sync.aligned.m8n8.x2.shared.b16 {%0,%1}, [%2];"
        : "=r"(r0), "=r"(r1) : "r"(addr));
}
__device__ __forceinline__ void ldmx4(unsigned& r0, unsigned& r1,
                                      unsigned& r2, unsigned& r3, uint32_t addr) {
    asm volatile(
        "ldmatrix.sync.aligned.m8n8.x4.shared.b16 {%0,%1,%2,%3}, [%4];"
        : "=r"(r0), "=r"(r1), "=r"(r2), "=r"(r3) : "r"(addr));
}
__device__ __forceinline__ uint32_t s2u(const void* p) {
    return (uint32_t)__cvta_generic_to_shared(p);
}
__device__ __forceinline__ void cpa16(uint32_t s, const void* g) {
    asm volatile("cp.async.cg.shared.global [%0], [%1], 16;" :: "r"(s), "l"(g));
}
__device__ __forceinline__ void cpa_commit() {
    asm volatile("cp.async.commit_group;" ::: "memory");
}
__device__ __forceinline__ void cpa_wait1() {
    asm volatile("cp.async.wait_group 1;" ::: "memory");
}
__device__ __forceinline__ void cpa_wait0() {
    asm volatile("cp.async.wait_group 0;" ::: "memory");
}

// =====================================================================
// x fp32 -> fp16 transcode
// =====================================================================
__global__ void __launch_bounds__(256) x_to_half(const float4* __restrict__ in,
                                                 uint2* __restrict__ out, int n4)
{
    const int i = blockIdx.x * 256 + threadIdx.x;
    if (i >= n4) return;
    float4 v = in[i];
    out[i] = make_uint2(fh2(v.x, v.y), fh2(v.z, v.w));
}

// =====================================================================
// Weight prepack: row-major fp32 [M,K] -> fp16 m16n8k16 A-fragment layout.
// =====================================================================
__global__ void __launch_bounds__(256) prepack_w(const float* __restrict__ W,
                                                 __half* __restrict__ P,
                                                 int M, int K)
{
    const int i = blockIdx.x * 256 + threadIdx.x;
    if (i >= M * K) return;
    const int m = i / K, k = i % K;
    const int mi = m >> 4, r = m & 15, g2 = r & 7, hf = r >> 3;
    const int ks = k >> 4, kk = k & 15;
    const int tgw = (kk >> 1) & 3, kh = kk >> 3, lo = kk & 1;
    P[((size_t)((mi * (K >> 4) + ks) * 32) + g2 * 4 + tgw) * 8 + (hf + 2 * kh) * 2 + lo]
        = __float2half_rn(W[i]);
}

// =====================================================================
// fp16 GEMM + BN (unchanged from R12 WIN).
// =====================================================================
#define BSTRIDE_ 120

template<bool OUT_HALF>
__global__ void __launch_bounds__(256, 2) gemm_f16(
    const uint4* __restrict__ Apk,
    const __half* __restrict__ Bsrc,
    void*        __restrict__ Cb,
    const float* __restrict__ gg, const float* __restrict__ bbp,
    const float* __restrict__ mmp, const float* __restrict__ vvp,
    int M, int N, int K)
{
    const int n0 = blockIdx.y * 112;
    const int z  = blockIdx.z;
    const __half* Bz = Bsrc + (size_t)z * K * N;

    __shared__ __align__(16) __half Bs[3][32 * BSTRIDE_];

    const int t    = threadIdx.x;
    const int lane = t & 31, wid = t >> 5;
    const int g    = lane >> 2, tg = lane & 3;
    const int wm   = wid >> 1, wn = wid & 1;
    const int nkt  = K >> 5;
    const int kt16 = K >> 4;

    float4 acc[2][7];
    #pragma unroll
    for (int i = 0; i < 2; ++i)
        #pragma unroll
        for (int j = 0; j < 7; ++j) acc[i][j] = make_float4(0.f, 0.f, 0.f, 0.f);

    const int kr0 = t / 14, c0 = t % 14;
    const int idx1 = t + 256;
    const bool ok1 = idx1 < 448;
    const int kr1 = ok1 ? idx1 / 14 : 0;
    const int c1  = ok1 ? idx1 % 14 : 0;

    auto issue = [&](int kt) {
        __half* buf = Bs[kt % 3];
        cpa16(s2u(buf + kr0 * BSTRIDE_ + c0 * 8),
              Bz + (size_t)(kt * 32 + kr0) * N + n0 + c0 * 8);
        if (ok1)
            cpa16(s2u(buf + kr1 * BSTRIDE_ + c1 * 8),
                  Bz + (size_t)(kt * 32 + kr1) * N + n0 + c1 * 8);
        cpa_commit();
    };

    const int mi0 = blockIdx.x * 8 + wm * 2;

    issue(0);
    if (nkt > 1) issue(1);

    for (int kt = 0; kt < nkt; ++kt) {
        uint4 af[2][2];
        #pragma unroll
        for (int mt = 0; mt < 2; ++mt)
            #pragma unroll
            for (int ks = 0; ks < 2; ++ks)
                af[mt][ks] = Apk[(size_t)((mi0 + mt) * kt16 + kt * 2 + ks) * 32 + lane];

        if (kt + 1 < nkt) cpa_wait1(); else cpa_wait0();
        __syncthreads();
        if (kt + 2 < nkt) issue(kt + 2);

        const __half* buf = Bs[kt % 3];
        #pragma unroll
        for (int ks = 0; ks < 2; ++ks) {
            const uint32_t rowaddr = s2u(
                buf + (ks * 16 + (lane & 15)) * BSTRIDE_ + wn * 56);
            #pragma unroll
            for (int nt = 0; nt < 7; ++nt) {
                unsigned b0, b1;
                ldmx2t(b0, b1, rowaddr + nt * 16);
                mma16(acc[0][nt], af[0][ks], b0, b1);
                mma16(acc[1][nt], af[1][ks], b0, b1);
            }
        }
    }

    #pragma unroll
    for (int mt = 0; mt < 2; ++mt) {
        const int r0 = (mi0 + mt) * 16 + g;
        const int r1 = r0 + 8;
        const float s0 = gg[r0] * rsqrtf(vvp[r0] + EPSBN);
        const float t0 = bbp[r0] - mmp[r0] * s0;
        const float s1 = gg[r1] * rsqrtf(vvp[r1] + EPSBN);
        const float t1 = bbp[r1] - mmp[r1] * s1;
        #pragma unroll
        for (int nt = 0; nt < 7; ++nt) {
            const int c = n0 + wn * 56 + nt * 8 + tg * 2;
            float4 a = acc[mt][nt];
            if (OUT_HALF) {
                __half* C = (__half*)Cb + (size_t)z * M * N;
                *reinterpret_cast<unsigned*>(&C[(size_t)r0 * N + c]) =
                    fh2(a.x * s0 + t0, a.y * s0 + t0);
                *reinterpret_cast<unsigned*>(&C[(size_t)r1 * N + c]) =
                    fh2(a.z * s1 + t1, a.w * s1 + t1);
            } else {
                float* C = (float*)Cb + (size_t)z * M * N;
                *reinterpret_cast<float2*>(&C[(size_t)r0 * N + c]) =
                    make_float2(a.x * s0 + t0, a.y * s0 + t0);
                *reinterpret_cast<float2*>(&C[(size_t)r1 * N + c]) =
                    make_float2(a.z * s1 + t1, a.w * s1 + t1);
            }
        }
    }
}

// =====================================================================
// Depthwise 3x3 + BN; output scaled by SCALE*LOG2E, fp16 (unchanged)
// =====================================================================
__global__ void __launch_bounds__(256) dwconv_kernel(
    const float* __restrict__ dw_w,
    const float* __restrict__ gg, const float* __restrict__ bb,
    const float* __restrict__ mm, const float* __restrict__ vv)
{
    const int bc = blockIdx.x;
    const int b  = bc >> 7;
    const int c  = bc & 127;
    const int t  = threadIdx.x;

    __shared__ float tile[30][30];
    for (int i = t; i < 900; i += 256) (&tile[0][0])[i] = 0.f;
    __syncthreads();

    const __half* in = &g_qkv[((size_t)b * QKVO_ + c) * NN_];
    for (int n = t; n < NN_; n += 256)
        tile[n / WW_ + 1][n % WW_ + 1] = __half2float(in[n]);
    __syncthreads();

    float wv[9];
    #pragma unroll
    for (int k = 0; k < 9; ++k) wv[k] = dw_w[c * 9 + k];
    const float s  = gg[c] * rsqrtf(vv[c] + EPSBN);
    const float tt = bb[c] - mm[c] * s;
    const float qs = SCALE_ * LOG2E_;

    __half* outp = &g_qdw[((size_t)b * NHKD_ + c) * NN_];
    for (int n = t; n < NN_; n += 256) {
        const int y = n / WW_, x = n % WW_;
        float a = 0.f;
        #pragma unroll
        for (int ky = 0; ky < 3; ++ky)
            #pragma unroll
            for (int kx = 0; kx < 3; ++kx)
                a = fmaf(tile[y + ky][x + kx], wv[ky * 3 + kx], a);
        outp[n] = __float2half_rn((a * s + tt) * qs);
    }
}

// =====================================================================
// Flash attention: 112-query blocks (7 warps), 112-key chunks (= 4 image
// rows; 784 = 7*112, PV k exact 7x16, softmax rounds halved).
// K/V raw rows (stride 120 halves) via cp.async 3-buffer ring in dynamic
// smem (~64KB, 2 blocks/SM). S: ldmatrix.x2.trans; PV: ldmatrix x4/x2.
// smem layout (bytes): K 0..11520, V 11520..57600, Qf 57600..61184,
// bias 61184..64320.
// =====================================================================
#define ATT_SMEM_BYTES 64320
#define VSTR_ 120

__global__ void __launch_bounds__(224, 2) attn_f16(const float* __restrict__ ab)
{
    extern __shared__ __align__(16) unsigned char smx[];
    __half* Kraw = (__half*)smx;                    // 3 x 16 x 120
    __half* Vraw = (__half*)(smx + 11520);          // 3 x 64 x 120
    unsigned* Qf = (unsigned*)(smx + 57600);        // 7*32*4
    float* biasS = (float*)(smx + 61184);           // 784

    const int qt = blockIdx.x, h = blockIdx.y, b = blockIdx.z;
    const int q0 = qt * 112;
    const int t = threadIdx.x, lane = t & 31, wid = t >> 5;
    const int g = lane >> 2, tg = lane & 3;

    for (int i = t; i < 784; i += 224) biasS[i] = ab[h * 784 + i] * LOG2E_;

    // ---- Q staging (224 tasks): rows d=2p,2p+1 at 4 queries, A-frag layout ----
    {
        const int p = t / 28, q4 = t % 28;
        const __half* qrow = g_qdw + ((size_t)b * NHKD_ + h * KD_ + 2 * p) * NN_
                             + q0 + q4 * 4;
        uint2 r0 = *reinterpret_cast<const uint2*>(qrow);
        uint2 r1 = *reinterpret_cast<const uint2*>(qrow + NN_);
        __half2 A0 = *reinterpret_cast<__half2*>(&r0.x);
        __half2 A1 = *reinterpret_cast<__half2*>(&r0.y);
        __half2 B0 = *reinterpret_cast<__half2*>(&r1.x);
        __half2 B1 = *reinterpret_cast<__half2*>(&r1.y);
        unsigned u[4] = { h2u(__lows2half2(A0, B0)), h2u(__highs2half2(A0, B0)),
                          h2u(__lows2half2(A1, B1)), h2u(__highs2half2(A1, B1)) };
        #pragma unroll
        for (int e = 0; e < 4; ++e) {
            const int q = q4 * 4 + e;
            const int mi = q >> 4, r = q & 15;
            Qf[(mi * 32 + (r & 7) * 4 + (p & 3)) * 4 + ((r >> 3) + 2 * (p >> 2))] = u[e];
        }
    }

    const int qa = q0 + wid * 16 + g;
    const int qya = qa / WW_, qxa = qa % WW_;
    const int qyb = (qa + 8) / WW_, qxb = (qa + 8) % WW_;

    float M0 = -1e30f, M1 = -1e30f, L0 = 0.f, L1 = 0.f;
    float4 O[8];
    #pragma unroll
    for (int i = 0; i < 8; ++i) O[i] = make_float4(0.f, 0.f, 0.f, 0.f);

    const __half* kbase = &g_qkv[((size_t)b * QKVO_ + NHKD_ + h * KD_) * NN_];
    const __half* vbase = &g_qkv[((size_t)b * QKVO_ + 2 * NHKD_ + h * DV_) * NN_];

    // staging tasks: K 224 (16 rows x 14 groups), V 896 (64 x 14, 4/thread)
    const int krow = t / 14, kgrp = t % 14;
    int vrow[4], vgrp[4];
    #pragma unroll
    for (int j = 0; j < 4; ++j) {
        const int idx = t + 224 * j;
        vrow[j] = idx / 14; vgrp[j] = idx % 14;
    }

    auto issue = [&](int c) {
        __half* kb = Kraw + (c % 3) * (16 * VSTR_);
        __half* vb = Vraw + (c % 3) * (64 * VSTR_);
        const int n0c = c * 112;
        cpa16(s2u(kb + krow * VSTR_ + kgrp * 8),
              kbase + (size_t)krow * NN_ + n0c + kgrp * 8);
        #pragma unroll
        for (int j = 0; j < 4; ++j)
            cpa16(s2u(vb + vrow[j] * VSTR_ + vgrp[j] * 8),
                  vbase + (size_t)vrow[j] * NN_ + n0c + vgrp[j] * 8);
        cpa_commit();
    };

    issue(0);
    issue(1);
    __syncthreads();   // Q/bias staging visible

    const uint4 qfrag = *reinterpret_cast<const uint4*>(&Qf[(wid * 32 + lane) * 4]);

    for (int c = 0; c < 7; ++c) {
        if (c < 6) cpa_wait1(); else cpa_wait0();
        __syncthreads();
        if (c + 2 < 7) issue(c + 2);

        const __half* Kb = Kraw + (c % 3) * (16 * VSTR_);
        const __half* Vb = Vraw + (c % 3) * (64 * VSTR_);

        // ---- S = Q.K : 14 x (ldmatrix.x2.trans + mma) ----
        float4 S[14];
        #pragma unroll
        for (int i = 0; i < 14; ++i) S[i] = make_float4(0.f, 0.f, 0.f, 0.f);
        {
            const uint32_t krowaddr = s2u(Kb + (lane & 15) * VSTR_);
            #pragma unroll
            for (int nt = 0; nt < 14; ++nt) {
                unsigned b0, b1;
                ldmx2t(b0, b1, krowaddr + nt * 16);
                mma16(S[nt], qfrag, b0, b1);
            }
        }

        // ---- bias (chunk = image rows 4c..4c+3) ----
        int bya[4], byb[4];
        #pragma unroll
        for (int r = 0; r < 4; ++r) {
            bya[r] = abs(qya - (4 * c + r)) * WW_;
            byb[r] = abs(qyb - (4 * c + r)) * WW_;
        }
        #pragma unroll
        for (int nt = 0; nt < 14; ++nt) {
            const int c0 = nt * 8 + tg * 2, c1 = c0 + 1;
            const int r0 = c0 / 28, nx0 = c0 - r0 * 28;
            const int r1 = c1 / 28, nx1 = c1 - r1 * 28;
            S[nt].x += biasS[bya[r0] + abs(qxa - nx0)];
            S[nt].y += biasS[bya[r1] + abs(qxa - nx1)];
            S[nt].z += biasS[byb[r0] + abs(qxb - nx0)];
            S[nt].w += biasS[byb[r1] + abs(qxb - nx1)];
        }

        // ---- online softmax (log2 domain) ----
        float mx0 = -1e30f, mx1 = -1e30f;
        #pragma unroll
        for (int nt = 0; nt < 14; ++nt) {
            mx0 = fmaxf(mx0, fmaxf(S[nt].x, S[nt].y));
            mx1 = fmaxf(mx1, fmaxf(S[nt].z, S[nt].w));
        }
        mx0 = fmaxf(mx0, __shfl_xor_sync(0xffffffffu, mx0, 1));
        mx0 = fmaxf(mx0, __shfl_xor_sync(0xffffffffu, mx0, 2));
        mx1 = fmaxf(mx1, __shfl_xor_sync(0xffffffffu, mx1, 1));
        mx1 = fmaxf(mx1, __shfl_xor_sync(0xffffffffu, mx1, 2));
        const float nM0 = fmaxf(M0, mx0), nM1 = fmaxf(M1, mx1);
        const float cor0 = ex2f(M0 - nM0), cor1 = ex2f(M1 - nM1);
        M0 = nM0; M1 = nM1;
        float rs0 = 0.f, rs1 = 0.f;
        #pragma unroll
        for (int nt = 0; nt < 14; ++nt) {
            S[nt].x = ex2f(S[nt].x - nM0); rs0 += S[nt].x;
            S[nt].y = ex2f(S[nt].y - nM0); rs0 += S[nt].y;
            S[nt].z = ex2f(S[nt].z - nM1); rs1 += S[nt].z;
            S[nt].w = ex2f(S[nt].w - nM1); rs1 += S[nt].w;
        }
        rs0 += __shfl_xor_sync(0xffffffffu, rs0, 1);
        rs0 += __shfl_xor_sync(0xffffffffu, rs0, 2);
        rs1 += __shfl_xor_sync(0xffffffffu, rs1, 1);
        rs1 += __shfl_xor_sync(0xffffffffu, rs1, 2);
        L0 = L0 * cor0 + rs0;
        L1 = L1 * cor1 + rs1;
        #pragma unroll
        for (int i = 0; i < 8; ++i) {
            O[i].x *= cor0; O[i].y *= cor0;
            O[i].z *= cor1; O[i].w *= cor1;
        }

        // ---- P: registers only, 7 exact k16 fragments ----
        uint4 Pk[7];
        #pragma unroll
        for (int ks = 0; ks < 7; ++ks)
            Pk[ks] = make_uint4(fh2(S[2 * ks].x,     S[2 * ks].y),
                                fh2(S[2 * ks].z,     S[2 * ks].w),
                                fh2(S[2 * ks + 1].x, S[2 * ks + 1].y),
                                fh2(S[2 * ks + 1].z, S[2 * ks + 1].w));

        // ---- O += P.V : per nt (8 d-groups): 3x ldmx4 + 1x ldmx2, 7 mma ----
        {
            const uint32_t vl4 = s2u(Vb) + (lane & 7) * (VSTR_ * 2) + (lane >> 3) * 16;
            const uint32_t vl2 = s2u(Vb) + (lane & 7) * (VSTR_ * 2)
                                 + ((lane >> 3) & 1) * 16 + 192;
            #pragma unroll
            for (int nt = 0; nt < 8; ++nt) {
                const uint32_t base4 = vl4 + nt * 8 * (VSTR_ * 2);
                const uint32_t base2 = vl2 + nt * 8 * (VSTR_ * 2);
                unsigned r0, r1, r2, r3;
                ldmx4(r0, r1, r2, r3, base4);
                mma16(O[nt], Pk[0], r0, r1);
                mma16(O[nt], Pk[1], r2, r3);
                ldmx4(r0, r1, r2, r3, base4 + 64);
                mma16(O[nt], Pk[2], r0, r1);
                mma16(O[nt], Pk[3], r2, r3);
                ldmx4(r0, r1, r2, r3, base4 + 128);
                mma16(O[nt], Pk[4], r0, r1);
                mma16(O[nt], Pk[5], r2, r3);
                ldmx2(r0, r1, base2);
                mma16(O[nt], Pk[6], r0, r1);
            }
        }
    }

    // ---- normalize + relu + fp16 store ----
    const float i0 = 1.f / L0, i1 = 1.f / L1;
    __half* obase = g_att + ((size_t)b * DH_ + h * DV_) * NN_;
    #pragma unroll
    for (int nt = 0; nt < 8; ++nt) {
        const int d0 = nt * 8 + tg * 2;
        obase[(size_t)d0 * NN_ + qa]           = __float2half_rn(fmaxf(O[nt].x * i0, 0.f));
        obase[(size_t)(d0 + 1) * NN_ + qa]     = __float2half_rn(fmaxf(O[nt].y * i0, 0.f));
        obase[(size_t)d0 * NN_ + qa + 8]       = __float2half_rn(fmaxf(O[nt].z * i1, 0.f));
        obase[(size_t)(d0 + 1) * NN_ + qa + 8] = __float2half_rn(fmaxf(O[nt].w * i1, 0.f));
    }
}

// =====================================================================
// launch
// =====================================================================
extern "C" void kernel_launch(void* const* d_in, const int* in_sizes, int n_in,
                              void* d_out, int out_size)
{
    const float* x      = (const float*)d_in[0];
    const float* qkv_w  = (const float*)d_in[1];
    const float* qkv_g  = (const float*)d_in[2];
    const float* qkv_b  = (const float*)d_in[3];
    const float* qkv_m  = (const float*)d_in[4];
    const float* qkv_v  = (const float*)d_in[5];
    const float* dw_w   = (const float*)d_in[6];
    const float* dw_g   = (const float*)d_in[7];
    const float* dw_b   = (const float*)d_in[8];
    const float* dw_m   = (const float*)d_in[9];
    const float* dw_v   = (const float*)d_in[10];
    const float* ab     = (const float*)d_in[11];
    const float* proj_w = (const float*)d_in[12];
    const float* proj_g = (const float*)d_in[13];
    const float* proj_b = (const float*)d_in[14];
    const float* proj_m = (const float*)d_in[15];
    const float* proj_v = (const float*)d_in[16];
    float* out = (float*)d_out;

    void *p_qkv, *p_att, *p_x16, *p_wqkv, *p_wproj;
    cudaGetSymbolAddress(&p_qkv, g_qkv);
    cudaGetSymbolAddress(&p_att, g_att);
    cudaGetSymbolAddress(&p_x16, g_x16);
    cudaGetSymbolAddress(&p_wqkv, g_wqkv);
    cudaGetSymbolAddress(&p_wproj, g_wproj);

    cudaFuncSetAttribute(attn_f16,
                         cudaFuncAttributeMaxDynamicSharedMemorySize, ATT_SMEM_BYTES);

    // 0) prepack + transcode
    prepack_w<<<(QKVO_ * DIM_ + 255) / 256, 256>>>(qkv_w, (__half*)p_wqkv, QKVO_, DIM_);
    prepack_w<<<(DIM_ * DH_ + 255) / 256, 256>>>(proj_w, (__half*)p_wproj, DIM_, DH_);
    {
        const int n4 = BB_ * DIM_ * NN_ / 4;
        x_to_half<<<(n4 + 255) / 256, 256>>>((const float4*)x, (uint2*)p_x16, n4);
    }

    // 1) QKV 1x1 + BN : fp16 in -> fp16 out
    gemm_f16<true><<<dim3(QKVO_ / 128, NN_ / 112, BB_), 256>>>(
        (const uint4*)p_wqkv, (const __half*)p_x16, p_qkv,
        qkv_g, qkv_b, qkv_m, qkv_v, QKVO_, NN_, DIM_);

    // 2) depthwise 3x3 + BN (scaled for attention)
    dwconv_kernel<<<BB_ * NHKD_, 256>>>(dw_w, dw_g, dw_b, dw_m, dw_v);

    // 3) attention (relu folded in, fp16 out)
    attn_f16<<<dim3(NN_ / 112, HEADS_, BB_), 224, ATT_SMEM_BYTES>>>(ab);

    // 4) proj 1x1 + BN : fp16 in -> fp32 out
    gemm_f16<false><<<dim3(DIM_ / 128, NN_ / 112, BB_), 256>>>(
        (const uint4*)p_wproj, (const __half*)p_att, out,
        proj_g, proj_b, proj_m, proj_v, DIM_, NN_, DH_);
}

// round 14
// speedup vs baseline: 1.0663x; 1.0663x over previous
#include <cuda_runtime.h>
#include <cuda_fp16.h>
#include <cstdint>
#include <math.h>

#define BB_   32
#define DIM_  256
#define HEADS_ 8
#define KD_   16
#define DV_   64
#define NHKD_ 128
#define DH_   512
#define QKVO_ 768
#define WW_   28
#define NN_   784
#define EPSBN 1e-5f
#define SCALE_ 0.25f
#define LOG2E_ 1.4426950408889634f

// ---------------- scratch (fp16 intermediates) ----------------
__device__ __half g_qkv[(size_t)BB_ * QKVO_ * NN_ + 64];
__device__ __half g_qdw[(size_t)BB_ * NHKD_ * NN_ + 64];
__device__ __half g_att[(size_t)BB_ * DH_ * NN_ + 64];
__device__ __half g_x16[(size_t)BB_ * DIM_ * NN_ + 64];
__device__ __half g_wqkv[QKVO_ * DIM_];
__device__ __half g_wproj[DIM_ * DH_];

// ---------------- helpers ----------------
__device__ __forceinline__ float ex2f(float x) {
    float y; asm("ex2.approx.ftz.f32 %0, %1;" : "=f"(y) : "f"(x)); return y;
}
__device__ __forceinline__ unsigned fh2(float lo, float hi) {
    __half2 h = __floats2half2_rn(lo, hi);
    return *reinterpret_cast<unsigned*>(&h);
}
__device__ __forceinline__ unsigned h2u(__half2 h) {
    return *reinterpret_cast<unsigned*>(&h);
}
__device__ __forceinline__ void mma16(float4& c, const uint4& a, unsigned b0, unsigned b1) {
    asm volatile(
        "mma.sync.aligned.m16n8k16.row.col.f32.f16.f16.f32 "
        "{%0,%1,%2,%3},{%4,%5,%6,%7},{%8,%9},{%0,%1,%2,%3};"
        : "+f"(c.x), "+f"(c.y), "+f"(c.z), "+f"(c.w)
        : "r"(a.x), "r"(a.y), "r"(a.z), "r"(a.w), "r"(b0), "r"(b1));
}
__device__ __forceinline__ void ldmx2t(unsigned& r0, unsigned& r1, uint32_t addr) {
    asm volatile(
        "ldmatrix.sync.aligned.m8n8.x2.trans.shared.b16 {%0,%1}, [%2];"
        : "=r"(r0), "=r"(r1) : "r"(addr));
}
__device__ __forceinline__ void ldmx4(unsigned& r0, unsigned& r1,
                                      unsigned& r2, unsigned& r3, uint32_t addr) {
    asm volatile(
        "ldmatrix.sync.aligned.m8n8.x4.shared.b16 {%0,%1,%2,%3}, [%4];"
        : "=r"(r0), "=r"(r1), "=r"(r2), "=r"(r3) : "r"(addr));
}
__device__ __forceinline__ uint32_t s2u(const void* p) {
    return (uint32_t)__cvta_generic_to_shared(p);
}
__device__ __forceinline__ void cpa16(uint32_t s, const void* g) {
    asm volatile("cp.async.cg.shared.global [%0], [%1], 16;" :: "r"(s), "l"(g));
}
__device__ __forceinline__ void cpa_commit() {
    asm volatile("cp.async.commit_group;" ::: "memory");
}
__device__ __forceinline__ void cpa_wait1() {
    asm volatile("cp.async.wait_group 1;" ::: "memory");
}
__device__ __forceinline__ void cpa_wait0() {
    asm volatile("cp.async.wait_group 0;" ::: "memory");
}

// =====================================================================
// Fused prep: x transcode + both weight prepacks in ONE launch (overlap).
// blockIdx.x < NX4B           : x fp32->fp16 (uint2 tasks)
// next NWQB blocks            : qkv_w prepack
// last NWPB blocks            : proj_w prepack
// =====================================================================
#define NX4_  (BB_ * DIM_ * NN_ / 4)
#define NX4B_ ((NX4_ + 255) / 256)
#define NWQ_  (QKVO_ * DIM_)
#define NWQB_ ((NWQ_ + 255) / 256)
#define NWP_  (DIM_ * DH_)
#define NWPB_ ((NWP_ + 255) / 256)

__device__ __forceinline__ void prepack_one(const float* __restrict__ W,
                                            __half* __restrict__ P,
                                            int i, int K)
{
    const int m = i / K, k = i % K;
    const int mi = m >> 4, r = m & 15, g2 = r & 7, hf = r >> 3;
    const int ks = k >> 4, kk = k & 15;
    const int tgw = (kk >> 1) & 3, kh = kk >> 3, lo = kk & 1;
    P[((size_t)((mi * (K >> 4) + ks) * 32) + g2 * 4 + tgw) * 8 + (hf + 2 * kh) * 2 + lo]
        = __float2half_rn(W[i]);
}

__global__ void __launch_bounds__(256) prep_all(
    const float4* __restrict__ x4, uint2* __restrict__ x16,
    const float* __restrict__ wq, __half* __restrict__ pq,
    const float* __restrict__ wp, __half* __restrict__ pp)
{
    const int bx = blockIdx.x;
    if (bx < NX4B_) {
        const int i = bx * 256 + threadIdx.x;
        if (i < NX4_) {
            float4 v = x4[i];
            x16[i] = make_uint2(fh2(v.x, v.y), fh2(v.z, v.w));
        }
    } else if (bx < NX4B_ + NWQB_) {
        const int i = (bx - NX4B_) * 256 + threadIdx.x;
        if (i < NWQ_) prepack_one(wq, pq, i, DIM_);
    } else {
        const int i = (bx - NX4B_ - NWQB_) * 256 + threadIdx.x;
        if (i < NWP_) prepack_one(wp, pp, i, DH_);
    }
}

// =====================================================================
// fp16 GEMM + BN (R12 WIN, unchanged).
// =====================================================================
#define BSTRIDE_ 120

template<bool OUT_HALF>
__global__ void __launch_bounds__(256, 2) gemm_f16(
    const uint4* __restrict__ Apk,
    const __half* __restrict__ Bsrc,
    void*        __restrict__ Cb,
    const float* __restrict__ gg, const float* __restrict__ bbp,
    const float* __restrict__ mmp, const float* __restrict__ vvp,
    int M, int N, int K)
{
    const int n0 = blockIdx.y * 112;
    const int z  = blockIdx.z;
    const __half* Bz = Bsrc + (size_t)z * K * N;

    __shared__ __align__(16) __half Bs[3][32 * BSTRIDE_];

    const int t    = threadIdx.x;
    const int lane = t & 31, wid = t >> 5;
    const int g    = lane >> 2, tg = lane & 3;
    const int wm   = wid >> 1, wn = wid & 1;
    const int nkt  = K >> 5;
    const int kt16 = K >> 4;

    float4 acc[2][7];
    #pragma unroll
    for (int i = 0; i < 2; ++i)
        #pragma unroll
        for (int j = 0; j < 7; ++j) acc[i][j] = make_float4(0.f, 0.f, 0.f, 0.f);

    const int kr0 = t / 14, c0 = t % 14;
    const int idx1 = t + 256;
    const bool ok1 = idx1 < 448;
    const int kr1 = ok1 ? idx1 / 14 : 0;
    const int c1  = ok1 ? idx1 % 14 : 0;

    auto issue = [&](int kt) {
        __half* buf = Bs[kt % 3];
        cpa16(s2u(buf + kr0 * BSTRIDE_ + c0 * 8),
              Bz + (size_t)(kt * 32 + kr0) * N + n0 + c0 * 8);
        if (ok1)
            cpa16(s2u(buf + kr1 * BSTRIDE_ + c1 * 8),
                  Bz + (size_t)(kt * 32 + kr1) * N + n0 + c1 * 8);
        cpa_commit();
    };

    const int mi0 = blockIdx.x * 8 + wm * 2;

    issue(0);
    if (nkt > 1) issue(1);

    for (int kt = 0; kt < nkt; ++kt) {
        uint4 af[2][2];
        #pragma unroll
        for (int mt = 0; mt < 2; ++mt)
            #pragma unroll
            for (int ks = 0; ks < 2; ++ks)
                af[mt][ks] = Apk[(size_t)((mi0 + mt) * kt16 + kt * 2 + ks) * 32 + lane];

        if (kt + 1 < nkt) cpa_wait1(); else cpa_wait0();
        __syncthreads();
        if (kt + 2 < nkt) issue(kt + 2);

        const __half* buf = Bs[kt % 3];
        #pragma unroll
        for (int ks = 0; ks < 2; ++ks) {
            const uint32_t rowaddr = s2u(
                buf + (ks * 16 + (lane & 15)) * BSTRIDE_ + wn * 56);
            #pragma unroll
            for (int nt = 0; nt < 7; ++nt) {
                unsigned b0, b1;
                ldmx2t(b0, b1, rowaddr + nt * 16);
                mma16(acc[0][nt], af[0][ks], b0, b1);
                mma16(acc[1][nt], af[1][ks], b0, b1);
            }
        }
    }

    #pragma unroll
    for (int mt = 0; mt < 2; ++mt) {
        const int r0 = (mi0 + mt) * 16 + g;
        const int r1 = r0 + 8;
        const float s0 = gg[r0] * rsqrtf(vvp[r0] + EPSBN);
        const float t0 = bbp[r0] - mmp[r0] * s0;
        const float s1 = gg[r1] * rsqrtf(vvp[r1] + EPSBN);
        const float t1 = bbp[r1] - mmp[r1] * s1;
        #pragma unroll
        for (int nt = 0; nt < 7; ++nt) {
            const int c = n0 + wn * 56 + nt * 8 + tg * 2;
            float4 a = acc[mt][nt];
            if (OUT_HALF) {
                __half* C = (__half*)Cb + (size_t)z * M * N;
                *reinterpret_cast<unsigned*>(&C[(size_t)r0 * N + c]) =
                    fh2(a.x * s0 + t0, a.y * s0 + t0);
                *reinterpret_cast<unsigned*>(&C[(size_t)r1 * N + c]) =
                    fh2(a.z * s1 + t1, a.w * s1 + t1);
            } else {
                float* C = (float*)Cb + (size_t)z * M * N;
                *reinterpret_cast<float2*>(&C[(size_t)r0 * N + c]) =
                    make_float2(a.x * s0 + t0, a.y * s0 + t0);
                *reinterpret_cast<float2*>(&C[(size_t)r1 * N + c]) =
                    make_float2(a.z * s1 + t1, a.w * s1 + t1);
            }
        }
    }
}

// =====================================================================
// Depthwise 3x3 + BN; output scaled by SCALE*LOG2E, fp16 (unchanged)
// =====================================================================
__global__ void __launch_bounds__(256) dwconv_kernel(
    const float* __restrict__ dw_w,
    const float* __restrict__ gg, const float* __restrict__ bb,
    const float* __restrict__ mm, const float* __restrict__ vv)
{
    const int bc = blockIdx.x;
    const int b  = bc >> 7;
    const int c  = bc & 127;
    const int t  = threadIdx.x;

    __shared__ float tile[30][30];
    for (int i = t; i < 900; i += 256) (&tile[0][0])[i] = 0.f;
    __syncthreads();

    const __half* in = &g_qkv[((size_t)b * QKVO_ + c) * NN_];
    for (int n = t; n < NN_; n += 256)
        tile[n / WW_ + 1][n % WW_ + 1] = __half2float(in[n]);
    __syncthreads();

    float wv[9];
    #pragma unroll
    for (int k = 0; k < 9; ++k) wv[k] = dw_w[c * 9 + k];
    const float s  = gg[c] * rsqrtf(vv[c] + EPSBN);
    const float tt = bb[c] - mm[c] * s;
    const float qs = SCALE_ * LOG2E_;

    __half* outp = &g_qdw[((size_t)b * NHKD_ + c) * NN_];
    for (int n = t; n < NN_; n += 256) {
        const int y = n / WW_, x = n % WW_;
        float a = 0.f;
        #pragma unroll
        for (int ky = 0; ky < 3; ++ky)
            #pragma unroll
            for (int kx = 0; kx < 3; ++kx)
                a = fmaf(tile[y + ky][x + kx], wv[ky * 3 + kx], a);
        outp[n] = __float2half_rn((a * s + tt) * qs);
    }
}

// =====================================================================
// Flash attention (R12 WIN structure): fp16 m16n8k16, 112 queries
// (7 warps), 56-key chunks, raw-row K/V via cp.async 3-ring,
// ldmatrix fragments, P in registers, exp2 softmax,
// + conditional O-rescale (skip when running max unchanged).
// =====================================================================
__global__ void __launch_bounds__(224, 2) attn_f16(const float* __restrict__ ab)
{
    __shared__ __align__(16) __half Kraw[3][16 * 72];
    __shared__ __align__(16) __half Vraw[3][64 * 72];
    __shared__ unsigned Qf[7 * 32 * 4];
    __shared__ float biasS[784];

    const int qt = blockIdx.x, h = blockIdx.y, b = blockIdx.z;
    const int q0 = qt * 112;
    const int t = threadIdx.x, lane = t & 31, wid = t >> 5;
    const int g = lane >> 2, tg = lane & 3;

    for (int i = t; i < 784; i += 224) biasS[i] = ab[h * 784 + i] * LOG2E_;

    // zero V pad keys 56..63 in all 3 buffers
    for (int i = t; i < 192; i += 224) {
        const int bufi = i / 64, row = i % 64;
        *reinterpret_cast<uint4*>(&Vraw[bufi][row * 72 + 56]) =
            make_uint4(0u, 0u, 0u, 0u);
    }

    // ---- Q staging (224 tasks): rows d=2p,2p+1 at 4 queries, A-frag layout ----
    {
        const int p = t / 28, q4 = t % 28;
        const __half* qrow = g_qdw + ((size_t)b * NHKD_ + h * KD_ + 2 * p) * NN_
                             + q0 + q4 * 4;
        uint2 r0 = *reinterpret_cast<const uint2*>(qrow);
        uint2 r1 = *reinterpret_cast<const uint2*>(qrow + NN_);
        __half2 A0 = *reinterpret_cast<__half2*>(&r0.x);
        __half2 A1 = *reinterpret_cast<__half2*>(&r0.y);
        __half2 B0 = *reinterpret_cast<__half2*>(&r1.x);
        __half2 B1 = *reinterpret_cast<__half2*>(&r1.y);
        unsigned u[4] = { h2u(__lows2half2(A0, B0)), h2u(__highs2half2(A0, B0)),
                          h2u(__lows2half2(A1, B1)), h2u(__highs2half2(A1, B1)) };
        #pragma unroll
        for (int e = 0; e < 4; ++e) {
            const int q = q4 * 4 + e;
            const int mi = q >> 4, r = q & 15;
            Qf[(mi * 32 + (r & 7) * 4 + (p & 3)) * 4 + ((r >> 3) + 2 * (p >> 2))] = u[e];
        }
    }

    const int qa = q0 + wid * 16 + g;
    const int qya = qa / WW_, qxa = qa % WW_;
    const int qyb = (qa + 8) / WW_, qxb = (qa + 8) % WW_;

    float M0 = -1e30f, M1 = -1e30f, L0 = 0.f, L1 = 0.f;
    float4 O[8];
    #pragma unroll
    for (int i = 0; i < 8; ++i) O[i] = make_float4(0.f, 0.f, 0.f, 0.f);

    const __half* kbase = &g_qkv[((size_t)b * QKVO_ + NHKD_ + h * KD_) * NN_];
    const __half* vbase = &g_qkv[((size_t)b * QKVO_ + 2 * NHKD_ + h * DV_) * NN_];

    const bool kok = t < 112;
    const int krow = kok ? t / 7 : 0, kgrp = kok ? t % 7 : 0;
    int vrow[2], vgrp[2];
    #pragma unroll
    for (int j = 0; j < 2; ++j) {
        const int idx = t + 224 * j;
        vrow[j] = idx / 7; vgrp[j] = idx % 7;
    }

    auto issue = [&](int c) {
        const int buf = c % 3;
        const int n0c = c * 56;
        if (kok)
            cpa16(s2u(&Kraw[buf][krow * 72 + kgrp * 8]),
                  kbase + (size_t)krow * NN_ + n0c + kgrp * 8);
        #pragma unroll
        for (int j = 0; j < 2; ++j)
            cpa16(s2u(&Vraw[buf][vrow[j] * 72 + vgrp[j] * 8]),
                  vbase + (size_t)vrow[j] * NN_ + n0c + vgrp[j] * 8);
        cpa_commit();
    };

    issue(0);
    issue(1);
    __syncthreads();

    const uint4 qfrag = *reinterpret_cast<const uint4*>(&Qf[(wid * 32 + lane) * 4]);

    for (int c = 0; c < 14; ++c) {
        if (c < 13) cpa_wait1(); else cpa_wait0();
        __syncthreads();
        if (c + 2 < 14) issue(c + 2);

        const __half* Kb = Kraw[c % 3];
        const __half* Vb = Vraw[c % 3];

        // ---- S = Q.K ----
        float4 S[7];
        #pragma unroll
        for (int i = 0; i < 7; ++i) S[i] = make_float4(0.f, 0.f, 0.f, 0.f);
        {
            const uint32_t krowaddr = s2u(Kb + (lane & 15) * 72);
            #pragma unroll
            for (int nt = 0; nt < 7; ++nt) {
                unsigned b0, b1;
                ldmx2t(b0, b1, krowaddr + nt * 16);
                mma16(S[nt], qfrag, b0, b1);
            }
        }

        // ---- bias ----
        const int ry0 = 2 * c, ry1 = 2 * c + 1;
        const int ba0 = abs(qya - ry0) * WW_, ba1 = abs(qya - ry1) * WW_;
        const int bb0 = abs(qyb - ry0) * WW_, bb1 = abs(qyb - ry1) * WW_;
        #pragma unroll
        for (int nt = 0; nt < 7; ++nt) {
            const int c0 = nt * 8 + tg * 2, c1 = c0 + 1;
            const int nx0 = (c0 < 28) ? c0 : c0 - 28;
            const int nx1 = (c1 < 28) ? c1 : c1 - 28;
            const bool r0b = c0 >= 28, r1b = c1 >= 28;
            S[nt].x += biasS[(r0b ? ba1 : ba0) + abs(qxa - nx0)];
            S[nt].y += biasS[(r1b ? ba1 : ba0) + abs(qxa - nx1)];
            S[nt].z += biasS[(r0b ? bb1 : bb0) + abs(qxb - nx0)];
            S[nt].w += biasS[(r1b ? bb1 : bb0) + abs(qxb - nx1)];
        }

        // ---- online softmax ----
        float mx0 = -1e30f, mx1 = -1e30f;
        #pragma unroll
        for (int nt = 0; nt < 7; ++nt) {
            mx0 = fmaxf(mx0, fmaxf(S[nt].x, S[nt].y));
            mx1 = fmaxf(mx1, fmaxf(S[nt].z, S[nt].w));
        }
        mx0 = fmaxf(mx0, __shfl_xor_sync(0xffffffffu, mx0, 1));
        mx0 = fmaxf(mx0, __shfl_xor_sync(0xffffffffu, mx0, 2));
        mx1 = fmaxf(mx1, __shfl_xor_sync(0xffffffffu, mx1, 1));
        mx1 = fmaxf(mx1, __shfl_xor_sync(0xffffffffu, mx1, 2));
        const float nM0 = fmaxf(M0, mx0), nM1 = fmaxf(M1, mx1);
        const bool upd = (nM0 != M0) || (nM1 != M1);
        if (upd) {
            const float cor0 = ex2f(M0 - nM0), cor1 = ex2f(M1 - nM1);
            L0 *= cor0; L1 *= cor1;
            #pragma unroll
            for (int i = 0; i < 8; ++i) {
                O[i].x *= cor0; O[i].y *= cor0;
                O[i].z *= cor1; O[i].w *= cor1;
            }
            M0 = nM0; M1 = nM1;
        }
        float rs0 = 0.f, rs1 = 0.f;
        #pragma unroll
        for (int nt = 0; nt < 7; ++nt) {
            S[nt].x = ex2f(S[nt].x - M0); rs0 += S[nt].x;
            S[nt].y = ex2f(S[nt].y - M0); rs0 += S[nt].y;
            S[nt].z = ex2f(S[nt].z - M1); rs1 += S[nt].z;
            S[nt].w = ex2f(S[nt].w - M1); rs1 += S[nt].w;
        }
        rs0 += __shfl_xor_sync(0xffffffffu, rs0, 1);
        rs0 += __shfl_xor_sync(0xffffffffu, rs0, 2);
        rs1 += __shfl_xor_sync(0xffffffffu, rs1, 1);
        rs1 += __shfl_xor_sync(0xffffffffu, rs1, 2);
        L0 += rs0;
        L1 += rs1;

        // ---- P: registers only (A-frag packing; keys 56..63 = zero pad) ----
        uint4 Pk[4];
        #pragma unroll
        for (int ks = 0; ks < 3; ++ks)
            Pk[ks] = make_uint4(fh2(S[2 * ks].x,     S[2 * ks].y),
                                fh2(S[2 * ks].z,     S[2 * ks].w),
                                fh2(S[2 * ks + 1].x, S[2 * ks + 1].y),
                                fh2(S[2 * ks + 1].z, S[2 * ks + 1].w));
        Pk[3] = make_uint4(fh2(S[6].x, S[6].y), fh2(S[6].z, S[6].w), 0u, 0u);

        // ---- O += P.V ----
        {
            const uint32_t vladdr = s2u(Vb) + (lane & 7) * 144 + (lane >> 3) * 16;
            #pragma unroll
            for (int nt = 0; nt < 8; ++nt) {
                const uint32_t a0 = vladdr + nt * 8 * 144;
                unsigned r0, r1, r2, r3;
                ldmx4(r0, r1, r2, r3, a0);
                mma16(O[nt], Pk[0], r0, r1);
                mma16(O[nt], Pk[1], r2, r3);
                ldmx4(r0, r1, r2, r3, a0 + 64);
                mma16(O[nt], Pk[2], r0, r1);
                mma16(O[nt], Pk[3], r2, r3);
            }
        }
    }

    // ---- normalize + relu + fp16 store ----
    const float i0 = 1.f / L0, i1 = 1.f / L1;
    __half* obase = g_att + ((size_t)b * DH_ + h * DV_) * NN_;
    #pragma unroll
    for (int nt = 0; nt < 8; ++nt) {
        const int d0 = nt * 8 + tg * 2;
        obase[(size_t)d0 * NN_ + qa]           = __float2half_rn(fmaxf(O[nt].x * i0, 0.f));
        obase[(size_t)(d0 + 1) * NN_ + qa]     = __float2half_rn(fmaxf(O[nt].y * i0, 0.f));
        obase[(size_t)d0 * NN_ + qa + 8]       = __float2half_rn(fmaxf(O[nt].z * i1, 0.f));
        obase[(size_t)(d0 + 1) * NN_ + qa + 8] = __float2half_rn(fmaxf(O[nt].w * i1, 0.f));
    }
}

// =====================================================================
// launch
// =====================================================================
extern "C" void kernel_launch(void* const* d_in, const int* in_sizes, int n_in,
                              void* d_out, int out_size)
{
    const float* x      = (const float*)d_in[0];
    const float* qkv_w  = (const float*)d_in[1];
    const float* qkv_g  = (const float*)d_in[2];
    const float* qkv_b  = (const float*)d_in[3];
    const float* qkv_m  = (const float*)d_in[4];
    const float* qkv_v  = (const float*)d_in[5];
    const float* dw_w   = (const float*)d_in[6];
    const float* dw_g   = (const float*)d_in[7];
    const float* dw_b   = (const float*)d_in[8];
    const float* dw_m   = (const float*)d_in[9];
    const float* dw_v   = (const float*)d_in[10];
    const float* ab     = (const float*)d_in[11];
    const float* proj_w = (const float*)d_in[12];
    const float* proj_g = (const float*)d_in[13];
    const float* proj_b = (const float*)d_in[14];
    const float* proj_m = (const float*)d_in[15];
    const float* proj_v = (const float*)d_in[16];
    float* out = (float*)d_out;

    void *p_qkv, *p_att, *p_x16, *p_wqkv, *p_wproj;
    cudaGetSymbolAddress(&p_qkv, g_qkv);
    cudaGetSymbolAddress(&p_att, g_att);
    cudaGetSymbolAddress(&p_x16, g_x16);
    cudaGetSymbolAddress(&p_wqkv, g_wqkv);
    cudaGetSymbolAddress(&p_wproj, g_wproj);

    // 0) fused prep: transcode + both prepacks (one launch)
    prep_all<<<NX4B_ + NWQB_ + NWPB_, 256>>>(
        (const float4*)x, (uint2*)p_x16,
        qkv_w, (__half*)p_wqkv, proj_w, (__half*)p_wproj);

    // 1) QKV 1x1 + BN : fp16 in -> fp16 out
    gemm_f16<true><<<dim3(QKVO_ / 128, NN_ / 112, BB_), 256>>>(
        (const uint4*)p_wqkv, (const __half*)p_x16, p_qkv,
        qkv_g, qkv_b, qkv_m, qkv_v, QKVO_, NN_, DIM_);

    // 2) depthwise 3x3 + BN (scaled for attention)
    dwconv_kernel<<<BB_ * NHKD_, 256>>>(dw_w, dw_g, dw_b, dw_m, dw_v);

    // 3) attention (relu folded in, fp16 out)
    attn_f16<<<dim3(NN_ / 112, HEADS_, BB_), 224>>>(ab);

    // 4) proj 1x1 + BN : fp16 in -> fp32 out
    gemm_f16<false><<<dim3(DIM_ / 128, NN_ / 112, BB_), 256>>>(
        (const uint4*)p_wproj, (const __half*)p_att, out,
        proj_g, proj_b, proj_m, proj_v, DIM_, NN_, DH_);
}